// round 12
// baseline (speedup 1.0000x reference)
#include <cuda_runtime.h>
#include <cuda_fp16.h>

#define Tq 2048
#define Eq 256
#define BT 16384        /* 8*2048 */
#define BHq 64
#define QSCALE 0.0901684417f   /* E^-0.5 * log2(e): scores in log2 domain */

// ---------------- scratch ----------------
__device__ __half g_xnh[BT*Eq];
__device__ __half g_qkvh[BT*768];     // 0..255 q(prescaled), 256..511 k, 512..767 v; col=h*32+d
__device__ __half g_vsc[BT*Eq];       // V * (1/l), layout [b][s][h*32+d]
__device__ __half g_xhh[BT*Eq];
__device__ float  g_xl[BT*Eq];
__device__ float  g_x2[BT*Eq];
__device__ __half g_x2h[BT*Eq];
__device__ __half g_wqkvT[768*256];   // [n][k]
__device__ __half g_wlinT[256*256];
__device__ __half g_wf1T[1024*256];
__device__ __half g_wf2T[256*1024];

// ---------------- helpers ----------------
__device__ __forceinline__ void mma_f16(float* c, const unsigned* a, const unsigned* b){
  asm volatile("mma.sync.aligned.m16n8k16.row.col.f32.f16.f16.f32 "
               "{%0,%1,%2,%3}, {%4,%5,%6,%7}, {%8,%9}, {%0,%1,%2,%3};\n"
               : "+f"(c[0]), "+f"(c[1]), "+f"(c[2]), "+f"(c[3])
               : "r"(a[0]), "r"(a[1]), "r"(a[2]), "r"(a[3]), "r"(b[0]), "r"(b[1]));
}
__device__ __forceinline__ void ldsm_x4(unsigned& r0, unsigned& r1, unsigned& r2, unsigned& r3,
                                        unsigned addr){
  asm volatile("ldmatrix.sync.aligned.m8n8.x4.shared.b16 {%0,%1,%2,%3}, [%4];\n"
               : "=r"(r0), "=r"(r1), "=r"(r2), "=r"(r3) : "r"(addr));
}
__device__ __forceinline__ void ldsm_x4_t(unsigned& r0, unsigned& r1, unsigned& r2, unsigned& r3,
                                          unsigned addr){
  asm volatile("ldmatrix.sync.aligned.m8n8.x4.trans.shared.b16 {%0,%1,%2,%3}, [%4];\n"
               : "=r"(r0), "=r"(r1), "=r"(r2), "=r"(r3) : "r"(addr));
}
// one MUFU op for two exponentials
__device__ __forceinline__ __half2 hex2(__half2 x){
  unsigned u = *(unsigned*)&x, y;
  asm("ex2.approx.f16x2 %0, %1;" : "=r"(y) : "r"(u));
  return *(__half2*)&y;
}
__device__ __forceinline__ unsigned ldh2(const __half* p){ return *(const unsigned*)p; }
__device__ __forceinline__ void stC(float* C, size_t idx, float v0, float v1){
  float2 o; o.x = v0; o.y = v1; *(float2*)&C[idx] = o;
}
__device__ __forceinline__ void stC(__half* C, size_t idx, float v0, float v1){
  *(__half2*)&C[idx] = __floats2half2_rn(v0, v1);
}
__device__ __forceinline__ unsigned smaddr(const void* p){
  return (unsigned)__cvta_generic_to_shared(p);
}
#define CPA16(dst, src) asm volatile("cp.async.cg.shared.global [%0], [%1], 16;\n" :: "r"(dst), "l"(src))
#define CPCOMMIT()      asm volatile("cp.async.commit_group;\n")
#define CPWAIT0()       asm volatile("cp.async.wait_group 0;\n")

// ---------------- fused weight prep: qkv pack + 3 transposes ----------------
__global__ void k_prep(const float* __restrict__ wq, const float* __restrict__ wk,
                       const float* __restrict__ wv, const float* __restrict__ w_lin,
                       const float* __restrict__ w_f1, const float* __restrict__ w_f2){
  __shared__ float t[32][33];
  int bid = blockIdx.x, tid = threadIdx.x;
  if (bid < 256){
    int idx = bid*256 + tid;
    int c = idx >> 8, e = idx & 255;
    int h = c >> 5, d = c & 31;
    int src = h*Eq*32 + e*32 + d;
    g_wqkvT[(      c)*256 + e] = __float2half(wq[src] * QSCALE);
    g_wqkvT[(256 + c)*256 + e] = __float2half(wk[src]);
    g_wqkvT[(512 + c)*256 + e] = __float2half(wv[src]);
    return;
  }
  const float* src; __half* dst; int N, K, tile;
  if (bid < 320){ tile = bid-256; src = w_lin; dst = g_wlinT; N = 256;  K = 256; }
  else if (bid < 576){ tile = bid-320; src = w_f1; dst = g_wf1T; N = 1024; K = 256; }
  else { tile = bid-576; src = w_f2; dst = g_wf2T; N = 256;  K = 1024; }
  int ntn = N >> 5;
  int n0 = (tile % ntn)*32, k0 = (tile / ntn)*32;
  int tx = tid & 31, ty = tid >> 5;
  #pragma unroll
  for (int j = 0; j < 4; j++)
    t[ty + 8*j][tx] = src[(size_t)(k0 + ty + 8*j)*N + n0 + tx];
  __syncthreads();
  #pragma unroll
  for (int j = 0; j < 4; j++)
    dst[(size_t)(n0 + ty + 8*j)*K + k0 + tx] = __float2half(t[tx][ty + 8*j]);
}

// ---------------- LayerNorm: warp per row; fp32 out optional ----------------
__global__ void k_ln(const float* __restrict__ in, const float* __restrict__ g,
                     const float* __restrict__ b, float* __restrict__ out,
                     __half* __restrict__ outh){
  int warp = threadIdx.x >> 5, lane = threadIdx.x & 31;
  int row = blockIdx.x*8 + warp;
  size_t base = (size_t)row*Eq + lane*8;
  float4 v0 = *(const float4*)&in[base];
  float4 v1 = *(const float4*)&in[base + 4];
  float s  = v0.x+v0.y+v0.z+v0.w + v1.x+v1.y+v1.z+v1.w;
  float s2 = v0.x*v0.x+v0.y*v0.y+v0.z*v0.z+v0.w*v0.w
           + v1.x*v1.x+v1.y*v1.y+v1.z*v1.z+v1.w*v1.w;
  #pragma unroll
  for (int o = 16; o > 0; o >>= 1){
    s  += __shfl_xor_sync(0xffffffffu, s,  o);
    s2 += __shfl_xor_sync(0xffffffffu, s2, o);
  }
  float mean = s * (1.0f/Eq);
  float var  = s2 * (1.0f/Eq) - mean*mean;
  float inv  = rsqrtf(var + 1e-5f);
  float4 ga = *(const float4*)&g[lane*8];
  float4 gb = *(const float4*)&g[lane*8 + 4];
  float4 ba = *(const float4*)&b[lane*8];
  float4 bb = *(const float4*)&b[lane*8 + 4];
  float o0 = (v0.x-mean)*inv*ga.x + ba.x;
  float o1 = (v0.y-mean)*inv*ga.y + ba.y;
  float o2 = (v0.z-mean)*inv*ga.z + ba.z;
  float o3 = (v0.w-mean)*inv*ga.w + ba.w;
  float o4 = (v1.x-mean)*inv*gb.x + bb.x;
  float o5 = (v1.y-mean)*inv*gb.y + bb.y;
  float o6 = (v1.z-mean)*inv*gb.z + bb.z;
  float o7 = (v1.w-mean)*inv*gb.w + bb.w;
  if (out){
    float4 w0; w0.x=o0; w0.y=o1; w0.z=o2; w0.w=o3;
    float4 w1; w1.x=o4; w1.y=o5; w1.z=o6; w1.w=o7;
    *(float4*)&out[base] = w0;
    *(float4*)&out[base+4] = w1;
  }
  __half2 h01 = __floats2half2_rn(o0,o1), h23 = __floats2half2_rn(o2,o3);
  __half2 h45 = __floats2half2_rn(o4,o5), h67 = __floats2half2_rn(o6,o7);
  uint4 u; u.x=*(unsigned*)&h01; u.y=*(unsigned*)&h23; u.z=*(unsigned*)&h45; u.w=*(unsigned*)&h67;
  *(uint4*)&outh[base] = u;
}

// ---------------- fp16 GEMM: 128x128 tiles, cp.async pipeline, ldmatrix frags ----------------
#define MM_SMEM (4*128*72*2)  /* 73728 bytes */
template<typename TC>
__global__ __launch_bounds__(256) void k_mm(
    const __half* __restrict__ A, const __half* __restrict__ Bt,
    const float* __restrict__ bias, const float* __restrict__ res,
    TC* __restrict__ C, int N, int K, int relu)
{
  extern __shared__ __half smp[];
  __half* As = smp;             // [2][128][72]
  __half* Bs = smp + 2*128*72;  // [2][128][72]
  const int SST = 128*72;
  int tid = threadIdx.x, lane = tid & 31, warp = tid >> 5;
  int r = lane >> 2, c = lane & 3;
  int wm = warp & 3, wn = warp >> 2;       // warp tile 32(m) x 64(n)
  int m0 = blockIdx.y*128, n0 = blockIdx.x*128;
  const __half* Ap = A + (size_t)m0*K;
  const __half* Bp = Bt + (size_t)n0*K;
  float acc[2][8][4] = {};
  int nk = K >> 6;
  int lrow = tid >> 1, lc0 = (tid & 1)*32;

  int g  = lane >> 3, lr = lane & 7;
  int arow = (g & 1)*8 + lr, acol = (g >> 1)*8;
  int brow = (g >> 1)*8 + lr, bcol = (g & 1)*8;
  unsigned aab[2], bab[4];
  #pragma unroll
  for (int mi = 0; mi < 2; mi++)
    aab[mi] = smaddr(&As[(wm*32 + mi*16 + arow)*72 + acol]);
  #pragma unroll
  for (int nj = 0; nj < 4; nj++)
    bab[nj] = smaddr(&Bs[(wn*64 + nj*16 + brow)*72 + bcol]);

  #define LOADT(stage, k0)  do {                                            \
    unsigned da = smaddr(&As[(stage)*SST + lrow*72 + lc0]);                 \
    const __half* sa = Ap + (size_t)lrow*K + (k0) + lc0;                    \
    CPA16(da, sa); CPA16(da+16, sa+8); CPA16(da+32, sa+16); CPA16(da+48, sa+24); \
    unsigned db = smaddr(&Bs[(stage)*SST + lrow*72 + lc0]);                 \
    const __half* sb = Bp + (size_t)lrow*K + (k0) + lc0;                    \
    CPA16(db, sb); CPA16(db+16, sb+8); CPA16(db+32, sb+16); CPA16(db+48, sb+24); \
    CPCOMMIT();                                                             \
  } while(0)

  LOADT(0, 0);
  for (int it = 0; it < nk; it++){
    unsigned stoff = (unsigned)(it & 1)*(SST*2);
    CPWAIT0();
    __syncthreads();
    if (it + 1 < nk) LOADT((it & 1)^1, (it+1) << 6);
    #pragma unroll
    for (int ks = 0; ks < 4; ks++){
      unsigned a[2][4], b[4][4];
      #pragma unroll
      for (int mi = 0; mi < 2; mi++)
        ldsm_x4(a[mi][0], a[mi][1], a[mi][2], a[mi][3], aab[mi] + stoff + ks*32);
      #pragma unroll
      for (int nj = 0; nj < 4; nj++)
        ldsm_x4(b[nj][0], b[nj][1], b[nj][2], b[nj][3], bab[nj] + stoff + ks*32);
      #pragma unroll
      for (int mi = 0; mi < 2; mi++)
        #pragma unroll
        for (int nj = 0; nj < 4; nj++){
          mma_f16(acc[mi][2*nj  ], a[mi], &b[nj][0]);
          mma_f16(acc[mi][2*nj+1], a[mi], &b[nj][2]);
        }
    }
  }
  #pragma unroll
  for (int mi = 0; mi < 2; mi++)
    #pragma unroll
    for (int ni = 0; ni < 8; ni++)
      #pragma unroll
      for (int hf = 0; hf < 2; hf++){
        int rr = m0 + wm*32 + mi*16 + r + hf*8;
        int cc = n0 + wn*64 + ni*8 + 2*c;
        float v0 = acc[mi][ni][hf*2  ];
        float v1 = acc[mi][ni][hf*2+1];
        if (bias){ v0 += bias[cc]; v1 += bias[cc+1]; }
        if (relu){ v0 = fmaxf(v0, 0.f); v1 = fmaxf(v1, 0.f); }
        if (res){
          float2 rv = *(const float2*)&res[(size_t)rr*N + cc];
          v0 += rv.x; v1 += rv.y;
        }
        stC(C, (size_t)rr*N + cc, v0, v1);
      }
}

// ---------------- fused FFN: out = x2 + relu(x2@W1+b1)@W2 + b2 ----------------
// block = 64 rows; loop 8 hidden-chunks of 128; H lives in smem; out accum in regs
#define FFN_SMEM 96256
__global__ __launch_bounds__(256, 2) void k_ffn(
    const __half* __restrict__ x2h, const float* __restrict__ b1,
    const float* __restrict__ b2, const float* __restrict__ res,
    float* __restrict__ out)
{
  extern __shared__ __half sm[];
  __half* X2s = sm;                 // 4 chunks x [64][72]
  __half* WB  = sm + 18432;         // 2 stages x 10240 halves
  __half* HS  = sm + 18432 + 20480; // 2 chunks x [64][72]
  int tid = threadIdx.x, lane = tid & 31, warp = tid >> 5;
  int r = lane >> 2, c = lane & 3;
  int wm = warp >> 1, wn = warp & 1;   // 4 m-groups of 16; 2 n-halves
  int m0 = blockIdx.x*64;
  int g  = lane >> 3, lr = lane & 7;
  int aoff = ((g & 1)*8 + lr)*72 + (g >> 1)*8;          // A-frag lane offset (72-pad tiles)
  int boff = ((g >> 1)*8 + lr)*72 + (g & 1)*8;          // B-frag lane offset (72-pad)
  int b2off = ((g >> 1)*8 + lr)*40 + (g & 1)*8;         // B-frag lane offset (40-pad W2 tiles)
  unsigned x2base = smaddr(X2s), wbase = smaddr(WB), hbase = smaddr(HS);

  // prologue: X2 tile (one group) + W1 chunk0 kc0 (one group)
  {
    int row = tid >> 2, part = tid & 3;
    #pragma unroll
    for (int kc = 0; kc < 4; kc++){
      unsigned d = x2base + (kc*4608 + row*72 + part*16)*2;
      const __half* s = x2h + (size_t)(m0+row)*256 + kc*64 + part*16;
      CPA16(d, s); CPA16(d+16, s+8);
    }
    CPCOMMIT();
  }
  int w1row = tid >> 1, w1half = tid & 1;
  #define LOADW1(cc, kc, stage) do {                                        \
    unsigned d = wbase + ((stage)*10240 + w1row*72 + w1half*32)*2;          \
    const __half* s = g_wf1T + (size_t)((cc)*128 + w1row)*256 + (kc)*64 + w1half*32; \
    CPA16(d, s); CPA16(d+16, s+8); CPA16(d+32, s+16); CPA16(d+48, s+24);    \
    CPCOMMIT();                                                             \
  } while(0)
  #define LOADW2(cc, p, stage) do {                                         \
    unsigned d = wbase + ((stage)*10240 + tid*40)*2;                        \
    const __half* s = g_wf2T + (size_t)tid*1024 + (cc)*128 + (p)*32;        \
    CPA16(d, s); CPA16(d+16, s+8); CPA16(d+32, s+16); CPA16(d+48, s+24);    \
    CPCOMMIT();                                                             \
  } while(0)

  LOADW1(0, 0, 0);
  float acc[16][4] = {};     // persistent out accum: 16m x 128n per warp
  for (int ch = 0; ch < 8; ch++){
    float acc2[8][4] = {};   // phase-A accum: 16m x 64n per warp
    // ---- phase A: H = relu(X2 @ W1c + b1c), 4 k-chunks ----
    #pragma unroll
    for (int kc = 0; kc < 4; kc++){
      int step = kc;                 // global step parity = step&1
      CPWAIT0();
      __syncthreads();
      // issue next load (1-ahead)
      if (kc < 3) LOADW1(ch, kc+1, (step+1)&1);
      else        LOADW2(ch, 0, (step+1)&1);
      unsigned wst = (unsigned)(step&1)*10240*2;
      #pragma unroll
      for (int ks = 0; ks < 4; ks++){
        unsigned a[4];
        ldsm_x4(a[0], a[1], a[2], a[3],
                x2base + (kc*4608 + wm*16*72)*2 + aoff*2 + ks*32);
        #pragma unroll
        for (int nj = 0; nj < 4; nj++){
          unsigned b0, b1c_, b2_, b3;
          ldsm_x4(b0, b1c_, b2_, b3,
                  wbase + wst + (wn*64 + nj*16)*72*2 + boff*2 + ks*32);
          unsigned bf0[2] = {b0, b1c_}, bf1[2] = {b2_, b3};
          mma_f16(acc2[2*nj  ], a, bf0);
          mma_f16(acc2[2*nj+1], a, bf1);
        }
      }
    }
    // phase A epilogue: bias + relu + store fp16 to HS
    #pragma unroll
    for (int ni = 0; ni < 8; ni++){
      int nglob = wn*64 + ni*8 + 2*c;
      float bb0 = b1[ch*128 + nglob], bb1 = b1[ch*128 + nglob + 1];
      #pragma unroll
      for (int hf = 0; hf < 2; hf++){
        float v0 = fmaxf(acc2[ni][hf*2  ] + bb0, 0.f);
        float v1 = fmaxf(acc2[ni][hf*2+1] + bb1, 0.f);
        int row = wm*16 + r + hf*8;
        __half* p = HS + (nglob>>6)*4608 + row*72 + (nglob & 63);
        *(__half2*)p = __floats2half2_rn(v0, v1);
      }
    }
    // ---- phase B: out += H @ W2c, 4 k-parts of 32 ----
    #pragma unroll
    for (int p = 0; p < 4; p++){
      int step = 4 + p;
      CPWAIT0();
      __syncthreads();     // also orders HS writes before reads (p==0)
      if (p < 3)            LOADW2(ch, p+1, (step+1)&1);
      else if (ch < 7)      LOADW1(ch+1, 0, (step+1)&1);
      unsigned wst = (unsigned)(step&1)*10240*2;
      #pragma unroll
      for (int ks = 0; ks < 2; ks++){
        unsigned a[4];
        int kcol = (p&1)*32 + ks*16;
        ldsm_x4(a[0], a[1], a[2], a[3],
                hbase + ((p>>1)*4608 + wm*16*72 + kcol)*2 + aoff*2);
        #pragma unroll
        for (int nj = 0; nj < 8; nj++){
          unsigned b0, b1c_, b2_, b3;
          ldsm_x4(b0, b1c_, b2_, b3,
                  wbase + wst + (wn*128 + nj*16)*40*2 + b2off*2 + ks*32);
          unsigned bf0[2] = {b0, b1c_}, bf1[2] = {b2_, b3};
          mma_f16(acc[2*nj  ], a, bf0);
          mma_f16(acc[2*nj+1], a, bf1);
        }
      }
    }
  }
  // final epilogue: + b2 + residual(x2 fp32), write fp32
  #pragma unroll
  for (int ni = 0; ni < 16; ni++){
    int n = wn*128 + ni*8 + 2*c;
    float bb0 = b2[n], bb1 = b2[n+1];
    #pragma unroll
    for (int hf = 0; hf < 2; hf++){
      int m = m0 + wm*16 + r + hf*8;
      float2 rv = *(const float2*)&res[(size_t)m*256 + n];
      stC(out, (size_t)m*256 + n,
          acc[ni][hf*2  ] + bb0 + rv.x,
          acc[ni][hf*2+1] + bb1 + rv.y);
    }
  }
}

// ---------------- pass 1: column sums of exp2(scores) over t >= s; writes V/l ----------------
__global__ __launch_bounds__(256, 3) void k_colsum(){
  __shared__ __half Ks[128][40];
  __shared__ __half Qs[2][128][40];
  __shared__ float red[8][32];
  __shared__ float Lsc[128];
  const int QST = 128*40*2;
  int s0 = blockIdx.x * 128;
  int z = blockIdx.y;
  int b = z >> 3, h = z & 7;
  int tid = threadIdx.x, lane = tid & 31, warp = tid >> 5;
  int r = lane >> 2, c = lane & 3;
  int wm = warp >> 2, wn = warp & 3;
  const __half* qb = g_qkvh + (size_t)(b*Tq)*768 + h*32;
  const __half* kb = qb + 256;
  const __half* vb = qb + 512;

  int g  = lane >> 3, lr = lane & 7;
  int arow = (g & 1)*8 + lr, acol = (g >> 1)*8;
  int brow = (g >> 1)*8 + lr, bcol = (g & 1)*8;
  unsigned qab[4], kab[2];
  #pragma unroll
  for (int mi = 0; mi < 4; mi++)
    qab[mi] = smaddr(&Qs[0][wm*64 + mi*16 + arow][acol]);
  #pragma unroll
  for (int nj = 0; nj < 2; nj++)
    kab[nj] = smaddr(&Ks[wn*32 + nj*16 + brow][bcol]);

  {
    int row = tid >> 1, col = (tid & 1)*16;
    *(uint4*)&Ks[row][col  ] = *(const uint4*)&kb[(size_t)(s0+row)*768 + col];
    *(uint4*)&Ks[row][col+8] = *(const uint4*)&kb[(size_t)(s0+row)*768 + col + 8];
  }
  int qrow = tid >> 1, qc0 = (tid & 1)*16;
  #define LOADQ(stage, t0) do {                                          \
    unsigned d = smaddr(&Qs[stage][qrow][qc0]);                          \
    const __half* s = qb + (size_t)((t0)+qrow)*768 + qc0;                \
    CPA16(d, s); CPA16(d+16, s+8);                                       \
    CPCOMMIT();                                                          \
  } while(0)

  LOADQ(0, s0);
  float lsum[8] = {};
  int ntile = (Tq - s0) >> 7;
  for (int it = 0; it < ntile; it++){
    unsigned stoff = (unsigned)(it & 1)*QST;
    CPWAIT0();
    __syncthreads();
    if (it + 1 < ntile) LOADQ((it & 1)^1, s0 + ((it+1) << 7));
    bool dg = (it == 0);
    unsigned kf[2][2][4];
    #pragma unroll
    for (int ks = 0; ks < 2; ks++)
      #pragma unroll
      for (int nj = 0; nj < 2; nj++)
        ldsm_x4(kf[ks][nj][0], kf[ks][nj][1], kf[ks][nj][2], kf[ks][nj][3],
                kab[nj] + ks*32);
    #pragma unroll
    for (int mih = 0; mih < 2; mih++){
      float sc[2][4][4] = {};
      #pragma unroll
      for (int ks = 0; ks < 2; ks++){
        unsigned a[2][4];
        #pragma unroll
        for (int mi = 0; mi < 2; mi++)
          ldsm_x4(a[mi][0], a[mi][1], a[mi][2], a[mi][3],
                  qab[mih*2 + mi] + stoff + ks*32);
        #pragma unroll
        for (int mi = 0; mi < 2; mi++)
          #pragma unroll
          for (int nj = 0; nj < 2; nj++){
            mma_f16(sc[mi][2*nj  ], a[mi], &kf[ks][nj][0]);
            mma_f16(sc[mi][2*nj+1], a[mi], &kf[ks][nj][2]);
          }
      }
      #pragma unroll
      for (int mi = 0; mi < 2; mi++)
        #pragma unroll
        for (int ni = 0; ni < 4; ni++){
          __half2 elo = hex2(__floats2half2_rn(sc[mi][ni][0], sc[mi][ni][1]));
          __half2 ehi = hex2(__floats2half2_rn(sc[mi][ni][2], sc[mi][ni][3]));
          if (dg){
            int tg = wm*64 + (mih*2 + mi)*16 + r;
            int sg = wn*32 + ni*8 + 2*c;
            elo = __hmul2(elo, __floats2half2_rn(tg   >= sg ? 1.f:0.f, tg   >= sg+1 ? 1.f:0.f));
            ehi = __hmul2(ehi, __floats2half2_rn(tg+8 >= sg ? 1.f:0.f, tg+8 >= sg+1 ? 1.f:0.f));
          }
          __half2 e = __hadd2(elo, ehi);
          float2 f = __half22float2(e);
          lsum[ni*2  ] += f.x;
          lsum[ni*2+1] += f.y;
        }
    }
  }
  #pragma unroll
  for (int j = 0; j < 8; j++){
    float v = lsum[j];
    v += __shfl_xor_sync(0xffffffffu, v, 4);
    v += __shfl_xor_sync(0xffffffffu, v, 8);
    v += __shfl_xor_sync(0xffffffffu, v, 16);
    lsum[j] = v;
  }
  if (r == 0){
    #pragma unroll
    for (int ni = 0; ni < 4; ni++){
      red[warp][ni*8 + 2*c    ] = lsum[ni*2  ];
      red[warp][ni*8 + 2*c + 1] = lsum[ni*2+1];
    }
  }
  __syncthreads();
  if (tid < 128){
    int wn2 = tid >> 5, lc = tid & 31;
    float tot = red[wn2][lc] + red[4 + wn2][lc];
    Lsc[wn2*32 + lc] = 1.0f / tot;
  }
  __syncthreads();
  {
    int row = tid >> 1, col = (tid & 1)*16;
    float li = Lsc[row];
    __half2 l2 = __float2half2_rn(li);
    __half* dst = g_vsc + ((size_t)(b*Tq) + s0 + row)*Eq + h*32 + col;
    #pragma unroll
    for (int half = 0; half < 2; half++){
      uint4 u = *(const uint4*)&vb[(size_t)(s0+row)*768 + col + half*8];
      __half2* p = (__half2*)&u;
      p[0] = __hmul2(p[0], l2); p[1] = __hmul2(p[1], l2);
      p[2] = __hmul2(p[2], l2); p[3] = __hmul2(p[3], l2);
      *(uint4*)(dst + half*8) = u;
    }
  }
}

// ---------------- pass 2: fused flash AV; fp16 residual ----------------
__global__ __launch_bounds__(256, 3) void k_av(){
  __shared__ __half Qs[128][40];
  __shared__ __half Ks[2][64][40];
  __shared__ __half Vs[2][64][40];
  const int KST = 64*40*2;
  int tt = 15 - blockIdx.x;
  int z = blockIdx.y;
  int b = z >> 3, h = z & 7;
  int t0 = tt*128;
  int tid = threadIdx.x, lane = tid & 31, warp = tid >> 5;
  int r = lane >> 2, c = lane & 3;
  const __half* qb = g_qkvh + (size_t)(b*Tq)*768 + h*32;
  const __half* kb = qb + 256;
  const __half* vsc = g_vsc + (size_t)(b*Tq)*Eq + h*32;
  int row_l = tid >> 2, col_l = (tid & 3)*8;

  int g  = lane >> 3, lr = lane & 7;
  int brow = (g >> 1)*8 + lr, bcol = (g & 1)*8;
  int vrow = (g & 1)*8 + lr,  vcol = (g >> 1)*8;
  unsigned kab[4], vab[2];
  #pragma unroll
  for (int nj = 0; nj < 4; nj++)
    kab[nj] = smaddr(&Ks[0][nj*16 + brow][bcol]);
  #pragma unroll
  for (int nj = 0; nj < 2; nj++)
    vab[nj] = smaddr(&Vs[0][vrow][nj*16 + vcol]);

  #pragma unroll
  for (int i = 0; i < 2; i++)
    *(uint4*)&Qs[row_l+64*i][col_l] = *(const uint4*)&qb[(size_t)(t0+row_l+64*i)*768 + col_l];
  __syncthreads();
  unsigned qa[2][4];
  {
    int row = warp*16 + r;
    #pragma unroll
    for (int ks = 0; ks < 2; ks++){
      int kb2 = 16*ks + 2*c;
      qa[ks][0] = ldh2(&Qs[row  ][kb2  ]);
      qa[ks][1] = ldh2(&Qs[row+8][kb2  ]);
      qa[ks][2] = ldh2(&Qs[row  ][kb2+8]);
      qa[ks][3] = ldh2(&Qs[row+8][kb2+8]);
    }
  }
  int krow = tid >> 2, kch = (tid & 3)*8;
  #define LOADKV(stage, s0v) do {                                         \
    CPA16(smaddr(&Ks[stage][krow][kch]), kb + (size_t)((s0v)+krow)*768 + kch); \
    CPA16(smaddr(&Vs[stage][krow][kch]), vsc + (size_t)((s0v)+krow)*Eq + kch); \
    CPCOMMIT();                                                           \
  } while(0)

  float av[4][4] = {};
  int send = t0 + 64;
  LOADKV(0, 0);
  int st = 0;
  for (int s0 = 0; s0 <= send; s0 += 64, st ^= 1){
    unsigned stoff = (unsigned)st*KST;
    CPWAIT0();
    __syncthreads();
    if (s0 + 64 <= send) LOADKV(st^1, s0 + 64);
    float sc[8][4] = {};
    #pragma unroll
    for (int ks = 0; ks < 2; ks++){
      #pragma unroll
      for (int nj = 0; nj < 4; nj++){
        unsigned b0, b1, b2, b3;
        ldsm_x4(b0, b1, b2, b3, kab[nj] + stoff + ks*32);
        unsigned bf0[2] = {b0, b1};
        unsigned bf1[2] = {b2, b3};
        mma_f16(sc[2*nj  ], qa[ks], bf0);
        mma_f16(sc[2*nj+1], qa[ks], bf1);
      }
    }
    bool dg = (s0 + 63 > t0);
    int rbase = t0 + warp*16 + r;
    #pragma unroll
    for (int ks = 0; ks < 4; ks++){
      unsigned pa[4];
      #pragma unroll
      for (int half = 0; half < 2; half++){
        int ni = 2*ks + half;
        int sg0 = s0 + ni*8 + 2*c;
        __half2 elo = hex2(__floats2half2_rn(sc[ni][0], sc[ni][1]));
        __half2 ehi = hex2(__floats2half2_rn(sc[ni][2], sc[ni][3]));
        if (dg){
          elo = __hmul2(elo, __floats2half2_rn(rbase   >= sg0 ? 1.f:0.f, rbase   >= sg0+1 ? 1.f:0.f));
          ehi = __hmul2(ehi, __floats2half2_rn(rbase+8 >= sg0 ? 1.f:0.f, rbase+8 >= sg0+1 ? 1.f:0.f));
        }
        pa[half*2  ] = *(unsigned*)&elo;
        pa[half*2+1] = *(unsigned*)&ehi;
      }
      #pragma unroll
      for (int nj = 0; nj < 2; nj++){
        unsigned b0, b1, b2, b3;
        ldsm_x4_t(b0, b1, b2, b3, vab[nj] + stoff + ks*16*80);
        unsigned bf0[2] = {b0, b1};
        unsigned bf1[2] = {b2, b3};
        mma_f16(av[2*nj  ], pa, bf0);
        mma_f16(av[2*nj+1], pa, bf1);
      }
    }
  }
  #pragma unroll
  for (int ni = 0; ni < 4; ni++)
    #pragma unroll
    for (int hf = 0; hf < 2; hf++){
      int t = t0 + warp*16 + r + hf*8;
      int cc = h*32 + ni*8 + 2*c;
      size_t base = (size_t)(b*Tq + t)*Eq + cc;
      __half2 rh = *(const __half2*)&g_xnh[base];
      float2 rv = __half22float2(rh);
      *(__half2*)&g_xhh[base] = __floats2half2_rn(av[ni][hf*2] + rv.x,
                                                  av[ni][hf*2+1] + rv.y);
    }
}

// ---------------- host ----------------
static void* symaddr(const void* sym){
  void* p = nullptr;
  cudaGetSymbolAddress(&p, sym);
  return p;
}

extern "C" void kernel_launch(void* const* d_in, const int* in_sizes, int n_in,
                              void* d_out, int out_size){
  (void)in_sizes; (void)n_in; (void)out_size;
  const float* x     = (const float*)d_in[0];
  const float* wq    = (const float*)d_in[1];
  const float* wk    = (const float*)d_in[2];
  const float* wv    = (const float*)d_in[3];
  const float* w_lin = (const float*)d_in[4];
  const float* b_lin = (const float*)d_in[5];
  const float* g1    = (const float*)d_in[6];
  const float* beta1 = (const float*)d_in[7];
  const float* g2    = (const float*)d_in[8];
  const float* beta2 = (const float*)d_in[9];
  const float* w_f1  = (const float*)d_in[10];
  const float* b_f1  = (const float*)d_in[11];
  const float* w_f2  = (const float*)d_in[12];
  const float* b_f2  = (const float*)d_in[13];
  float* out = (float*)d_out;

  __half* xnh   = (__half*)symaddr(g_xnh);
  __half* qkvh  = (__half*)symaddr(g_qkvh);
  __half* xhh   = (__half*)symaddr(g_xhh);
  float*  xl    = (float*)symaddr(g_xl);
  float*  x2    = (float*)symaddr(g_x2);
  __half* x2h   = (__half*)symaddr(g_x2h);
  __half* wqkvT = (__half*)symaddr(g_wqkvT);
  __half* wlinT = (__half*)symaddr(g_wlinT);

  cudaFuncSetAttribute(k_mm<__half>, cudaFuncAttributeMaxDynamicSharedMemorySize, MM_SMEM);
  cudaFuncSetAttribute(k_mm<float>,  cudaFuncAttributeMaxDynamicSharedMemorySize, MM_SMEM);
  cudaFuncSetAttribute(k_ffn, cudaFuncAttributeMaxDynamicSharedMemorySize, FFN_SMEM);

  k_prep<<<832, 256>>>(wq, wk, wv, w_lin, w_f1, w_f2);
  k_ln<<<2048, 256>>>(x, g1, beta1, nullptr, xnh);
  k_mm<__half><<<dim3(6, 128), 256, MM_SMEM>>>(xnh, wqkvT, nullptr, nullptr, qkvh, 768, 256, 0);
  k_colsum<<<dim3(16, 64), 256>>>();
  k_av<<<dim3(16, 64), 256>>>();
  k_mm<float><<<dim3(2, 128), 256, MM_SMEM>>>(xhh, wlinT, b_lin, nullptr, xl, 256, 256, 0);
  k_ln<<<2048, 256>>>(xl, g2, beta2, x2, x2h);
  k_ffn<<<256, 256, FFN_SMEM>>>(x2h, b_f1, b_f2, x2, out);
}

// round 13
// speedup vs baseline: 1.0393x; 1.0393x over previous
#include <cuda_runtime.h>
#include <cuda_fp16.h>

#define Tq 2048
#define Eq 256
#define BT 16384        /* 8*2048 */
#define BHq 64
#define QSCALE 0.0901684417f   /* E^-0.5 * log2(e): scores in log2 domain */

// ---------------- scratch ----------------
__device__ __half g_xnh[BT*Eq];
__device__ __half g_qkvh[BT*768];     // 0..255 q(prescaled), 256..511 k, 512..767 v; col=h*32+d
__device__ __half g_vsc[BT*Eq];       // V * (1/l), layout [b][s][h*32+d]
__device__ __half g_xhh[BT*Eq];
__device__ float  g_xl[BT*Eq];
__device__ float  g_x2[BT*Eq];
__device__ __half g_x2h[BT*Eq];
__device__ __half g_h1h[(size_t)BT*1024];
__device__ __half g_wqkvT[768*256];   // [n][k]
__device__ __half g_wlinT[256*256];
__device__ __half g_wf1T[1024*256];
__device__ __half g_wf2T[256*1024];

// ---------------- helpers ----------------
__device__ __forceinline__ void mma_f16(float* c, const unsigned* a, const unsigned* b){
  asm volatile("mma.sync.aligned.m16n8k16.row.col.f32.f16.f16.f32 "
               "{%0,%1,%2,%3}, {%4,%5,%6,%7}, {%8,%9}, {%0,%1,%2,%3};\n"
               : "+f"(c[0]), "+f"(c[1]), "+f"(c[2]), "+f"(c[3])
               : "r"(a[0]), "r"(a[1]), "r"(a[2]), "r"(a[3]), "r"(b[0]), "r"(b[1]));
}
__device__ __forceinline__ void ldsm_x4(unsigned& r0, unsigned& r1, unsigned& r2, unsigned& r3,
                                        unsigned addr){
  asm volatile("ldmatrix.sync.aligned.m8n8.x4.shared.b16 {%0,%1,%2,%3}, [%4];\n"
               : "=r"(r0), "=r"(r1), "=r"(r2), "=r"(r3) : "r"(addr));
}
__device__ __forceinline__ void ldsm_x4_t(unsigned& r0, unsigned& r1, unsigned& r2, unsigned& r3,
                                          unsigned addr){
  asm volatile("ldmatrix.sync.aligned.m8n8.x4.trans.shared.b16 {%0,%1,%2,%3}, [%4];\n"
               : "=r"(r0), "=r"(r1), "=r"(r2), "=r"(r3) : "r"(addr));
}
// one MUFU op for two exponentials
__device__ __forceinline__ __half2 hex2(__half2 x){
  unsigned u = *(unsigned*)&x, y;
  asm("ex2.approx.f16x2 %0, %1;" : "=r"(y) : "r"(u));
  return *(__half2*)&y;
}
__device__ __forceinline__ unsigned ldh2(const __half* p){ return *(const unsigned*)p; }
__device__ __forceinline__ void stC(float* C, size_t idx, float v0, float v1){
  float2 o; o.x = v0; o.y = v1; *(float2*)&C[idx] = o;
}
__device__ __forceinline__ void stC(__half* C, size_t idx, float v0, float v1){
  *(__half2*)&C[idx] = __floats2half2_rn(v0, v1);
}
__device__ __forceinline__ unsigned smaddr(const void* p){
  return (unsigned)__cvta_generic_to_shared(p);
}
#define CPA16(dst, src) asm volatile("cp.async.cg.shared.global [%0], [%1], 16;\n" :: "r"(dst), "l"(src))
#define CPCOMMIT()      asm volatile("cp.async.commit_group;\n")
#define CPWAIT0()       asm volatile("cp.async.wait_group 0;\n")

// ---------------- fused weight prep: qkv pack + 3 transposes ----------------
__global__ void k_prep(const float* __restrict__ wq, const float* __restrict__ wk,
                       const float* __restrict__ wv, const float* __restrict__ w_lin,
                       const float* __restrict__ w_f1, const float* __restrict__ w_f2){
  __shared__ float t[32][33];
  int bid = blockIdx.x, tid = threadIdx.x;
  if (bid < 256){
    int idx = bid*256 + tid;
    int c = idx >> 8, e = idx & 255;
    int h = c >> 5, d = c & 31;
    int src = h*Eq*32 + e*32 + d;
    g_wqkvT[(      c)*256 + e] = __float2half(wq[src] * QSCALE);
    g_wqkvT[(256 + c)*256 + e] = __float2half(wk[src]);
    g_wqkvT[(512 + c)*256 + e] = __float2half(wv[src]);
    return;
  }
  const float* src; __half* dst; int N, K, tile;
  if (bid < 320){ tile = bid-256; src = w_lin; dst = g_wlinT; N = 256;  K = 256; }
  else if (bid < 576){ tile = bid-320; src = w_f1; dst = g_wf1T; N = 1024; K = 256; }
  else { tile = bid-576; src = w_f2; dst = g_wf2T; N = 256;  K = 1024; }
  int ntn = N >> 5;
  int n0 = (tile % ntn)*32, k0 = (tile / ntn)*32;
  int tx = tid & 31, ty = tid >> 5;
  #pragma unroll
  for (int j = 0; j < 4; j++)
    t[ty + 8*j][tx] = src[(size_t)(k0 + ty + 8*j)*N + n0 + tx];
  __syncthreads();
  #pragma unroll
  for (int j = 0; j < 4; j++)
    dst[(size_t)(n0 + ty + 8*j)*K + k0 + tx] = __float2half(t[tx][ty + 8*j]);
}

// ---------------- LayerNorm: warp per row; fp32 out optional ----------------
__global__ void k_ln(const float* __restrict__ in, const float* __restrict__ g,
                     const float* __restrict__ b, float* __restrict__ out,
                     __half* __restrict__ outh){
  int warp = threadIdx.x >> 5, lane = threadIdx.x & 31;
  int row = blockIdx.x*8 + warp;
  size_t base = (size_t)row*Eq + lane*8;
  float4 v0 = *(const float4*)&in[base];
  float4 v1 = *(const float4*)&in[base + 4];
  float s  = v0.x+v0.y+v0.z+v0.w + v1.x+v1.y+v1.z+v1.w;
  float s2 = v0.x*v0.x+v0.y*v0.y+v0.z*v0.z+v0.w*v0.w
           + v1.x*v1.x+v1.y*v1.y+v1.z*v1.z+v1.w*v1.w;
  #pragma unroll
  for (int o = 16; o > 0; o >>= 1){
    s  += __shfl_xor_sync(0xffffffffu, s,  o);
    s2 += __shfl_xor_sync(0xffffffffu, s2, o);
  }
  float mean = s * (1.0f/Eq);
  float var  = s2 * (1.0f/Eq) - mean*mean;
  float inv  = rsqrtf(var + 1e-5f);
  float4 ga = *(const float4*)&g[lane*8];
  float4 gb = *(const float4*)&g[lane*8 + 4];
  float4 ba = *(const float4*)&b[lane*8];
  float4 bb = *(const float4*)&b[lane*8 + 4];
  float o0 = (v0.x-mean)*inv*ga.x + ba.x;
  float o1 = (v0.y-mean)*inv*ga.y + ba.y;
  float o2 = (v0.z-mean)*inv*ga.z + ba.z;
  float o3 = (v0.w-mean)*inv*ga.w + ba.w;
  float o4 = (v1.x-mean)*inv*gb.x + bb.x;
  float o5 = (v1.y-mean)*inv*gb.y + bb.y;
  float o6 = (v1.z-mean)*inv*gb.z + bb.z;
  float o7 = (v1.w-mean)*inv*gb.w + bb.w;
  if (out){
    float4 w0; w0.x=o0; w0.y=o1; w0.z=o2; w0.w=o3;
    float4 w1; w1.x=o4; w1.y=o5; w1.z=o6; w1.w=o7;
    *(float4*)&out[base] = w0;
    *(float4*)&out[base+4] = w1;
  }
  __half2 h01 = __floats2half2_rn(o0,o1), h23 = __floats2half2_rn(o2,o3);
  __half2 h45 = __floats2half2_rn(o4,o5), h67 = __floats2half2_rn(o6,o7);
  uint4 u; u.x=*(unsigned*)&h01; u.y=*(unsigned*)&h23; u.z=*(unsigned*)&h45; u.w=*(unsigned*)&h67;
  *(uint4*)&outh[base] = u;
}

// ---------------- fp16 GEMM: 128x128 tiles, cp.async pipeline, ldmatrix frags ----------------
#define MM_SMEM (4*128*72*2)  /* 73728 bytes */
template<typename TC>
__global__ __launch_bounds__(256) void k_mm(
    const __half* __restrict__ A, const __half* __restrict__ Bt,
    const float* __restrict__ bias, const float* __restrict__ res,
    TC* __restrict__ C, int N, int K, int relu)
{
  extern __shared__ __half smp[];
  __half* As = smp;             // [2][128][72]
  __half* Bs = smp + 2*128*72;  // [2][128][72]
  const int SST = 128*72;
  int tid = threadIdx.x, lane = tid & 31, warp = tid >> 5;
  int r = lane >> 2, c = lane & 3;
  int wm = warp & 3, wn = warp >> 2;       // warp tile 32(m) x 64(n)
  int m0 = blockIdx.y*128, n0 = blockIdx.x*128;
  const __half* Ap = A + (size_t)m0*K;
  const __half* Bp = Bt + (size_t)n0*K;
  float acc[2][8][4] = {};
  int nk = K >> 6;
  int lrow = tid >> 1, lc0 = (tid & 1)*32;

  int g  = lane >> 3, lr = lane & 7;
  int arow = (g & 1)*8 + lr, acol = (g >> 1)*8;
  int brow = (g >> 1)*8 + lr, bcol = (g & 1)*8;
  unsigned aab[2], bab[4];
  #pragma unroll
  for (int mi = 0; mi < 2; mi++)
    aab[mi] = smaddr(&As[(wm*32 + mi*16 + arow)*72 + acol]);
  #pragma unroll
  for (int nj = 0; nj < 4; nj++)
    bab[nj] = smaddr(&Bs[(wn*64 + nj*16 + brow)*72 + bcol]);

  #define LOADT(stage, k0)  do {                                            \
    unsigned da = smaddr(&As[(stage)*SST + lrow*72 + lc0]);                 \
    const __half* sa = Ap + (size_t)lrow*K + (k0) + lc0;                    \
    CPA16(da, sa); CPA16(da+16, sa+8); CPA16(da+32, sa+16); CPA16(da+48, sa+24); \
    unsigned db = smaddr(&Bs[(stage)*SST + lrow*72 + lc0]);                 \
    const __half* sb = Bp + (size_t)lrow*K + (k0) + lc0;                    \
    CPA16(db, sb); CPA16(db+16, sb+8); CPA16(db+32, sb+16); CPA16(db+48, sb+24); \
    CPCOMMIT();                                                             \
  } while(0)

  LOADT(0, 0);
  for (int it = 0; it < nk; it++){
    unsigned stoff = (unsigned)(it & 1)*(SST*2);
    CPWAIT0();
    __syncthreads();
    if (it + 1 < nk) LOADT((it & 1)^1, (it+1) << 6);
    #pragma unroll
    for (int ks = 0; ks < 4; ks++){
      unsigned a[2][4], b[4][4];
      #pragma unroll
      for (int mi = 0; mi < 2; mi++)
        ldsm_x4(a[mi][0], a[mi][1], a[mi][2], a[mi][3], aab[mi] + stoff + ks*32);
      #pragma unroll
      for (int nj = 0; nj < 4; nj++)
        ldsm_x4(b[nj][0], b[nj][1], b[nj][2], b[nj][3], bab[nj] + stoff + ks*32);
      #pragma unroll
      for (int mi = 0; mi < 2; mi++)
        #pragma unroll
        for (int nj = 0; nj < 4; nj++){
          mma_f16(acc[mi][2*nj  ], a[mi], &b[nj][0]);
          mma_f16(acc[mi][2*nj+1], a[mi], &b[nj][2]);
        }
    }
  }
  #pragma unroll
  for (int mi = 0; mi < 2; mi++)
    #pragma unroll
    for (int ni = 0; ni < 8; ni++)
      #pragma unroll
      for (int hf = 0; hf < 2; hf++){
        int rr = m0 + wm*32 + mi*16 + r + hf*8;
        int cc = n0 + wn*64 + ni*8 + 2*c;
        float v0 = acc[mi][ni][hf*2  ];
        float v1 = acc[mi][ni][hf*2+1];
        if (bias){ v0 += bias[cc]; v1 += bias[cc+1]; }
        if (relu){ v0 = fmaxf(v0, 0.f); v1 = fmaxf(v1, 0.f); }
        if (res){
          float2 rv = *(const float2*)&res[(size_t)rr*N + cc];
          v0 += rv.x; v1 += rv.y;
        }
        stC(C, (size_t)rr*N + cc, v0, v1);
      }
}

// ---------------- pass 1: column sums of exp2(scores) over t >= s; writes V/l ----------------
__global__ __launch_bounds__(256, 3) void k_colsum(){
  __shared__ __half Ks[128][40];
  __shared__ __half Qs[2][128][40];
  __shared__ float red[8][32];
  __shared__ float Lsc[128];
  const int QST = 128*40*2;
  int s0 = blockIdx.x * 128;
  int z = blockIdx.y;
  int b = z >> 3, h = z & 7;
  int tid = threadIdx.x, lane = tid & 31, warp = tid >> 5;
  int r = lane >> 2, c = lane & 3;
  int wm = warp >> 2, wn = warp & 3;
  const __half* qb = g_qkvh + (size_t)(b*Tq)*768 + h*32;
  const __half* kb = qb + 256;
  const __half* vb = qb + 512;

  int g  = lane >> 3, lr = lane & 7;
  int arow = (g & 1)*8 + lr, acol = (g >> 1)*8;
  int brow = (g >> 1)*8 + lr, bcol = (g & 1)*8;
  unsigned qab[4], kab[2];
  #pragma unroll
  for (int mi = 0; mi < 4; mi++)
    qab[mi] = smaddr(&Qs[0][wm*64 + mi*16 + arow][acol]);
  #pragma unroll
  for (int nj = 0; nj < 2; nj++)
    kab[nj] = smaddr(&Ks[wn*32 + nj*16 + brow][bcol]);

  {
    int row = tid >> 1, col = (tid & 1)*16;
    *(uint4*)&Ks[row][col  ] = *(const uint4*)&kb[(size_t)(s0+row)*768 + col];
    *(uint4*)&Ks[row][col+8] = *(const uint4*)&kb[(size_t)(s0+row)*768 + col + 8];
  }
  int qrow = tid >> 1, qc0 = (tid & 1)*16;
  #define LOADQ(stage, t0) do {                                          \
    unsigned d = smaddr(&Qs[stage][qrow][qc0]);                          \
    const __half* s = qb + (size_t)((t0)+qrow)*768 + qc0;                \
    CPA16(d, s); CPA16(d+16, s+8);                                       \
    CPCOMMIT();                                                          \
  } while(0)

  LOADQ(0, s0);
  float lsum[8] = {};
  int ntile = (Tq - s0) >> 7;
  for (int it = 0; it < ntile; it++){
    unsigned stoff = (unsigned)(it & 1)*QST;
    CPWAIT0();
    __syncthreads();
    if (it + 1 < ntile) LOADQ((it & 1)^1, s0 + ((it+1) << 7));
    bool dg = (it == 0);
    unsigned kf[2][2][4];
    #pragma unroll
    for (int ks = 0; ks < 2; ks++)
      #pragma unroll
      for (int nj = 0; nj < 2; nj++)
        ldsm_x4(kf[ks][nj][0], kf[ks][nj][1], kf[ks][nj][2], kf[ks][nj][3],
                kab[nj] + ks*32);
    #pragma unroll
    for (int mih = 0; mih < 2; mih++){
      float sc[2][4][4] = {};
      #pragma unroll
      for (int ks = 0; ks < 2; ks++){
        unsigned a[2][4];
        #pragma unroll
        for (int mi = 0; mi < 2; mi++)
          ldsm_x4(a[mi][0], a[mi][1], a[mi][2], a[mi][3],
                  qab[mih*2 + mi] + stoff + ks*32);
        #pragma unroll
        for (int mi = 0; mi < 2; mi++)
          #pragma unroll
          for (int nj = 0; nj < 2; nj++){
            mma_f16(sc[mi][2*nj  ], a[mi], &kf[ks][nj][0]);
            mma_f16(sc[mi][2*nj+1], a[mi], &kf[ks][nj][2]);
          }
      }
      #pragma unroll
      for (int mi = 0; mi < 2; mi++)
        #pragma unroll
        for (int ni = 0; ni < 4; ni++){
          __half2 elo = hex2(__floats2half2_rn(sc[mi][ni][0], sc[mi][ni][1]));
          __half2 ehi = hex2(__floats2half2_rn(sc[mi][ni][2], sc[mi][ni][3]));
          if (dg){
            int tg = wm*64 + (mih*2 + mi)*16 + r;
            int sg = wn*32 + ni*8 + 2*c;
            elo = __hmul2(elo, __floats2half2_rn(tg   >= sg ? 1.f:0.f, tg   >= sg+1 ? 1.f:0.f));
            ehi = __hmul2(ehi, __floats2half2_rn(tg+8 >= sg ? 1.f:0.f, tg+8 >= sg+1 ? 1.f:0.f));
          }
          __half2 e = __hadd2(elo, ehi);
          float2 f = __half22float2(e);
          lsum[ni*2  ] += f.x;
          lsum[ni*2+1] += f.y;
        }
    }
  }
  #pragma unroll
  for (int j = 0; j < 8; j++){
    float v = lsum[j];
    v += __shfl_xor_sync(0xffffffffu, v, 4);
    v += __shfl_xor_sync(0xffffffffu, v, 8);
    v += __shfl_xor_sync(0xffffffffu, v, 16);
    lsum[j] = v;
  }
  if (r == 0){
    #pragma unroll
    for (int ni = 0; ni < 4; ni++){
      red[warp][ni*8 + 2*c    ] = lsum[ni*2  ];
      red[warp][ni*8 + 2*c + 1] = lsum[ni*2+1];
    }
  }
  __syncthreads();
  if (tid < 128){
    int wn2 = tid >> 5, lc = tid & 31;
    float tot = red[wn2][lc] + red[4 + wn2][lc];
    Lsc[wn2*32 + lc] = 1.0f / tot;
  }
  __syncthreads();
  {
    int row = tid >> 1, col = (tid & 1)*16;
    float li = Lsc[row];
    __half2 l2 = __float2half2_rn(li);
    __half* dst = g_vsc + ((size_t)(b*Tq) + s0 + row)*Eq + h*32 + col;
    #pragma unroll
    for (int half = 0; half < 2; half++){
      uint4 u = *(const uint4*)&vb[(size_t)(s0+row)*768 + col + half*8];
      __half2* p = (__half2*)&u;
      p[0] = __hmul2(p[0], l2); p[1] = __hmul2(p[1], l2);
      p[2] = __hmul2(p[2], l2); p[3] = __hmul2(p[3], l2);
      *(uint4*)(dst + half*8) = u;
    }
  }
}

// ---------------- pass 2: fused flash AV; fp16 residual ----------------
__global__ __launch_bounds__(256, 3) void k_av(){
  __shared__ __half Qs[128][40];
  __shared__ __half Ks[2][64][40];
  __shared__ __half Vs[2][64][40];
  const int KST = 64*40*2;
  int tt = 15 - blockIdx.x;
  int z = blockIdx.y;
  int b = z >> 3, h = z & 7;
  int t0 = tt*128;
  int tid = threadIdx.x, lane = tid & 31, warp = tid >> 5;
  int r = lane >> 2, c = lane & 3;
  const __half* qb = g_qkvh + (size_t)(b*Tq)*768 + h*32;
  const __half* kb = qb + 256;
  const __half* vsc = g_vsc + (size_t)(b*Tq)*Eq + h*32;
  int row_l = tid >> 2, col_l = (tid & 3)*8;

  int g  = lane >> 3, lr = lane & 7;
  int brow = (g >> 1)*8 + lr, bcol = (g & 1)*8;
  int vrow = (g & 1)*8 + lr,  vcol = (g >> 1)*8;
  unsigned kab[4], vab[2];
  #pragma unroll
  for (int nj = 0; nj < 4; nj++)
    kab[nj] = smaddr(&Ks[0][nj*16 + brow][bcol]);
  #pragma unroll
  for (int nj = 0; nj < 2; nj++)
    vab[nj] = smaddr(&Vs[0][vrow][nj*16 + vcol]);

  #pragma unroll
  for (int i = 0; i < 2; i++)
    *(uint4*)&Qs[row_l+64*i][col_l] = *(const uint4*)&qb[(size_t)(t0+row_l+64*i)*768 + col_l];
  __syncthreads();
  unsigned qa[2][4];
  {
    int row = warp*16 + r;
    #pragma unroll
    for (int ks = 0; ks < 2; ks++){
      int kb2 = 16*ks + 2*c;
      qa[ks][0] = ldh2(&Qs[row  ][kb2  ]);
      qa[ks][1] = ldh2(&Qs[row+8][kb2  ]);
      qa[ks][2] = ldh2(&Qs[row  ][kb2+8]);
      qa[ks][3] = ldh2(&Qs[row+8][kb2+8]);
    }
  }
  int krow = tid >> 2, kch = (tid & 3)*8;
  #define LOADKV(stage, s0v) do {                                         \
    CPA16(smaddr(&Ks[stage][krow][kch]), kb + (size_t)((s0v)+krow)*768 + kch); \
    CPA16(smaddr(&Vs[stage][krow][kch]), vsc + (size_t)((s0v)+krow)*Eq + kch); \
    CPCOMMIT();                                                           \
  } while(0)

  float av[4][4] = {};
  int send = t0 + 64;
  LOADKV(0, 0);
  int st = 0;
  for (int s0 = 0; s0 <= send; s0 += 64, st ^= 1){
    unsigned stoff = (unsigned)st*KST;
    CPWAIT0();
    __syncthreads();
    if (s0 + 64 <= send) LOADKV(st^1, s0 + 64);
    float sc[8][4] = {};
    #pragma unroll
    for (int ks = 0; ks < 2; ks++){
      #pragma unroll
      for (int nj = 0; nj < 4; nj++){
        unsigned b0, b1, b2, b3;
        ldsm_x4(b0, b1, b2, b3, kab[nj] + stoff + ks*32);
        unsigned bf0[2] = {b0, b1};
        unsigned bf1[2] = {b2, b3};
        mma_f16(sc[2*nj  ], qa[ks], bf0);
        mma_f16(sc[2*nj+1], qa[ks], bf1);
      }
    }
    bool dg = (s0 + 63 > t0);
    int rbase = t0 + warp*16 + r;
    #pragma unroll
    for (int ks = 0; ks < 4; ks++){
      unsigned pa[4];
      #pragma unroll
      for (int half = 0; half < 2; half++){
        int ni = 2*ks + half;
        int sg0 = s0 + ni*8 + 2*c;
        __half2 elo = hex2(__floats2half2_rn(sc[ni][0], sc[ni][1]));
        __half2 ehi = hex2(__floats2half2_rn(sc[ni][2], sc[ni][3]));
        if (dg){
          elo = __hmul2(elo, __floats2half2_rn(rbase   >= sg0 ? 1.f:0.f, rbase   >= sg0+1 ? 1.f:0.f));
          ehi = __hmul2(ehi, __floats2half2_rn(rbase+8 >= sg0 ? 1.f:0.f, rbase+8 >= sg0+1 ? 1.f:0.f));
        }
        pa[half*2  ] = *(unsigned*)&elo;
        pa[half*2+1] = *(unsigned*)&ehi;
      }
      #pragma unroll
      for (int nj = 0; nj < 2; nj++){
        unsigned b0, b1, b2, b3;
        ldsm_x4_t(b0, b1, b2, b3, vab[nj] + stoff + ks*16*80);
        unsigned bf0[2] = {b0, b1};
        unsigned bf1[2] = {b2, b3};
        mma_f16(av[2*nj  ], pa, bf0);
        mma_f16(av[2*nj+1], pa, bf1);
      }
    }
  }
  #pragma unroll
  for (int ni = 0; ni < 4; ni++)
    #pragma unroll
    for (int hf = 0; hf < 2; hf++){
      int t = t0 + warp*16 + r + hf*8;
      int cc = h*32 + ni*8 + 2*c;
      size_t base = (size_t)(b*Tq + t)*Eq + cc;
      __half2 rh = *(const __half2*)&g_xnh[base];
      float2 rv = __half22float2(rh);
      *(__half2*)&g_xhh[base] = __floats2half2_rn(av[ni][hf*2] + rv.x,
                                                  av[ni][hf*2+1] + rv.y);
    }
}

// ---------------- host ----------------
static void* symaddr(const void* sym){
  void* p = nullptr;
  cudaGetSymbolAddress(&p, sym);
  return p;
}

extern "C" void kernel_launch(void* const* d_in, const int* in_sizes, int n_in,
                              void* d_out, int out_size){
  (void)in_sizes; (void)n_in; (void)out_size;
  const float* x     = (const float*)d_in[0];
  const float* wq    = (const float*)d_in[1];
  const float* wk    = (const float*)d_in[2];
  const float* wv    = (const float*)d_in[3];
  const float* w_lin = (const float*)d_in[4];
  const float* b_lin = (const float*)d_in[5];
  const float* g1    = (const float*)d_in[6];
  const float* beta1 = (const float*)d_in[7];
  const float* g2    = (const float*)d_in[8];
  const float* beta2 = (const float*)d_in[9];
  const float* w_f1  = (const float*)d_in[10];
  const float* b_f1  = (const float*)d_in[11];
  const float* w_f2  = (const float*)d_in[12];
  const float* b_f2  = (const float*)d_in[13];
  float* out = (float*)d_out;

  __half* xnh   = (__half*)symaddr(g_xnh);
  __half* qkvh  = (__half*)symaddr(g_qkvh);
  __half* xhh   = (__half*)symaddr(g_xhh);
  float*  xl    = (float*)symaddr(g_xl);
  float*  x2    = (float*)symaddr(g_x2);
  __half* x2h   = (__half*)symaddr(g_x2h);
  __half* h1h   = (__half*)symaddr(g_h1h);
  __half* wqkvT = (__half*)symaddr(g_wqkvT);
  __half* wlinT = (__half*)symaddr(g_wlinT);
  __half* wf1T  = (__half*)symaddr(g_wf1T);
  __half* wf2T  = (__half*)symaddr(g_wf2T);

  cudaFuncSetAttribute(k_mm<__half>, cudaFuncAttributeMaxDynamicSharedMemorySize, MM_SMEM);
  cudaFuncSetAttribute(k_mm<float>,  cudaFuncAttributeMaxDynamicSharedMemorySize, MM_SMEM);

  k_prep<<<832, 256>>>(wq, wk, wv, w_lin, w_f1, w_f2);
  k_ln<<<2048, 256>>>(x, g1, beta1, nullptr, xnh);
  k_mm<__half><<<dim3(6, 128), 256, MM_SMEM>>>(xnh, wqkvT, nullptr, nullptr, qkvh, 768, 256, 0);
  k_colsum<<<dim3(16, 64), 256>>>();
  k_av<<<dim3(16, 64), 256>>>();
  k_mm<float><<<dim3(2, 128), 256, MM_SMEM>>>(xhh, wlinT, b_lin, nullptr, xl, 256, 256, 0);
  k_ln<<<2048, 256>>>(xl, g2, beta2, x2, x2h);
  k_mm<__half><<<dim3(8, 128), 256, MM_SMEM>>>(x2h, wf1T, b_f1, nullptr, h1h, 1024, 256, 1);
  k_mm<float><<<dim3(2, 128), 256, MM_SMEM>>>(h1h, wf2T, b_f2, x2, out, 256, 1024, 0);
}